// round 10
// baseline (speedup 1.0000x reference)
#include <cuda_runtime.h>
#include <math.h>

#define HALF_DT 0.005f
#define BATCH 32
#define DM    2048
#define DV    2047
#define DL    512
#define NC    4          // K chunks
#define KC    128        // K per chunk
#define DPC   16         // output d-rows per CTA
#define HALO  4
#define ROWS  24         // DPC + 2*HALO
#define NT    512
#define GRID  128
#define ZSTR  (KC + 4)   // 132: conflict-free LDS.128 (4*lane mod 32)
#define EST   33         // epilogue tile stride
#define BUFSZ (BATCH * ZSTR + ROWS * ZSTR)   // 4224 + 3168 = 7392 floats

extern __shared__ float smem[];

__global__ void __launch_bounds__(NT, 1)
fused_kernel(const float* __restrict__ z0,
             const float* __restrict__ h,
             const float* __restrict__ W,
             const float* __restrict__ bias,
             float* __restrict__ out) {
    const int tid   = threadIdx.x;
    const int lane  = tid & 31;
    const int w     = tid >> 5;              // 0..15
    const int dbase = blockIdx.x * DPC;

    // prefetch registers for one chunk: z 1024 f4 (2/thr), W 768 f4 (2/thr, 2nd guarded)
    float4 pz0, pz1, pw0, pw1;

#define LOADC(c) do {                                                          \
        int kb = (c) * KC;                                                     \
        { int f = tid;       int b_ = f >> 5, k4 = f & 31;                     \
          pz0 = *((const float4*)(z0 + b_ * DL + kb) + k4); }                  \
        { int f = tid + 512; int b_ = f >> 5, k4 = f & 31;                     \
          pz1 = *((const float4*)(z0 + b_ * DL + kb) + k4); }                  \
        { int f = tid;       int r_ = f >> 5, k4 = f & 31;                     \
          int d_ = dbase - HALO + r_; d_ = min(max(d_, 0), DM - 2);            \
          pw0 = *((const float4*)(W + (size_t)d_ * DL + kb) + k4); }           \
        if (tid < 256) { int f = tid + 512; int r_ = f >> 5, k4 = f & 31;      \
          int d_ = dbase - HALO + r_; d_ = min(max(d_, 0), DM - 2);            \
          pw1 = *((const float4*)(W + (size_t)d_ * DL + kb) + k4); }           \
    } while (0)

#define STSC(base) do {                                                        \
        float* zs_ = (base); float* ws_ = (base) + BATCH * ZSTR;               \
        { int f = tid;       int b_ = f >> 5, k4 = f & 31;                     \
          *((float4*)(zs_ + b_ * ZSTR) + k4) = pz0; }                          \
        { int f = tid + 512; int b_ = f >> 5, k4 = f & 31;                     \
          *((float4*)(zs_ + b_ * ZSTR) + k4) = pz1; }                          \
        { int f = tid;       int r_ = f >> 5, k4 = f & 31;                     \
          *((float4*)(ws_ + r_ * ZSTR) + k4) = pw0; }                          \
        if (tid < 256) { int f = tid + 512; int r_ = f >> 5, k4 = f & 31;      \
          *((float4*)(ws_ + r_ * ZSTR) + k4) = pw1; }                          \
    } while (0)

    // accumulators: warps 0..11 own local rows 2w, 2w+1 (covers all 24)
    float a00 = 0.f, a01 = 0.f, a02 = 0.f, a03 = 0.f;
    float a10 = 0.f, a11 = 0.f, a12 = 0.f, a13 = 0.f;

    LOADC(0);
    STSC(smem);
    __syncthreads();

#pragma unroll
    for (int c = 0; c < NC; c++) {
        if (c < NC - 1) LOADC(c + 1);        // LDGs in flight under compute
        float* buf = smem + (c & 1) * BUFSZ;
        if (w < 12) {
            const float4* zr = (const float4*)(buf + lane * ZSTR);
            const float4* w0 = (const float4*)(buf + BATCH * ZSTR + (2 * w    ) * ZSTR);
            const float4* w1 = (const float4*)(buf + BATCH * ZSTR + (2 * w + 1) * ZSTR);
#pragma unroll 8
            for (int k = 0; k < KC / 4; k++) {
                float4 z = zr[k];
                float4 p = w0[k];            // warp-uniform -> broadcast
                a00 += z.x * p.x; a01 += z.y * p.y; a02 += z.z * p.z; a03 += z.w * p.w;
                float4 q = w1[k];
                a10 += z.x * q.x; a11 += z.y * q.y; a12 += z.z * q.z; a13 += z.w * q.w;
            }
        }
        __syncthreads();                      // all reads of buf done
        if (c < NC - 1) {
            STSC(smem + ((c + 1) & 1) * BUFSZ);
            __syncthreads();
        }
    }

    // ---------------- epilogue: local Neumann solve ----------------
    // tiles reuse buffer 0 (chunk 3 computed on buf1; barrier above separates)
    float* svt = smem;                        // [24][33]
    float* ht  = smem + ROWS * EST;           // [24][33]
    float* y1t = smem + 2 * ROWS * EST;
    float* y2t = smem + 3 * ROWS * EST;

    if (w < 12) {
        int r0 = 2 * w, r1 = 2 * w + 1;
        int d0 = dbase - HALO + r0, d1 = dbase - HALO + r1;
        int dc0 = min(max(d0, 0), DV - 1);    // full clamp: no OOB even if LDG hoisted
        int dc1 = min(max(d1, 0), DV - 1);
        float s0 = (a00 + a01) + (a02 + a03);
        float s1 = (a10 + a11) + (a12 + a13);
        svt[r0 * EST + lane] = (d0 >= 0 && d0 < DV)
            ? HALF_DT * tanhf(s0 + __ldg(bias + dc0)) : 0.f;
        svt[r1 * EST + lane] = (d1 >= 0 && d1 < DV)
            ? HALF_DT * tanhf(s1 + __ldg(bias + dc1)) : 0.f;
    }
    // h tile; OOB rows clamped (their contributions killed by sv=0)
    for (int idx = tid; idx < ROWS * BATCH; idx += NT) {
        int b_ = idx / ROWS, r_ = idx - b_ * ROWS;
        int d_ = dbase - HALO + r_;
        d_ = min(max(d_, 0), DM - 1);
        ht[r_ * EST + b_] = h[(size_t)b_ * DM + d_];
    }
    __syncthreads();

    // pass 1: y1 = N h, rows 1..22
    for (int idx = tid; idx < BATCH * 22; idx += NT) {
        int r_ = (idx >> 5) + 1, b_ = idx & 31;
        y1t[r_ * EST + b_] = svt[r_ * EST + b_] * ht[(r_ + 1) * EST + b_]
                           - svt[(r_ - 1) * EST + b_] * ht[(r_ - 1) * EST + b_];
    }
    __syncthreads();
    // pass 2: y2 = N y1, rows 2..21
    for (int idx = tid; idx < BATCH * 20; idx += NT) {
        int r_ = (idx >> 5) + 2, b_ = idx & 31;
        y2t[r_ * EST + b_] = svt[r_ * EST + b_] * y1t[(r_ + 1) * EST + b_]
                           - svt[(r_ - 1) * EST + b_] * y1t[(r_ - 1) * EST + b_];
    }
    __syncthreads();
    // pass 3 + output: rows 4..19 -> d in [dbase, dbase+16), coalesced store
    {
        int b_ = tid >> 4, j = tid & 15;
        int r_ = j + HALO;
        float y3 = svt[r_ * EST + b_] * y2t[(r_ + 1) * EST + b_]
                 - svt[(r_ - 1) * EST + b_] * y2t[(r_ - 1) * EST + b_];
        float x = ht[r_ * EST + b_]
                + 2.f * (y1t[r_ * EST + b_] + y2t[r_ * EST + b_] + y3);
        out[(size_t)b_ * DM + dbase + j] = x;
    }
}

// ---------------------------------------------------------------------------
extern "C" void kernel_launch(void* const* d_in, const int* in_sizes, int n_in,
                              void* d_out, int out_size) {
    const float* z0   = (const float*)d_in[0];   // (32, 512)
    const float* h    = (const float*)d_in[1];   // (32, 2048)
    const float* W    = (const float*)d_in[2];   // (2047, 512)
    const float* bias = (const float*)d_in[3];   // (2047,)
    float* out = (float*)d_out;                  // (32, 2048)

    const int smemB = 2 * BUFSZ * (int)sizeof(float);   // 59136 B
    static bool attr_done = false;
    if (!attr_done) {
        cudaFuncSetAttribute(fused_kernel,
                             cudaFuncAttributeMaxDynamicSharedMemorySize, smemB);
        attr_done = true;
    }
    fused_kernel<<<GRID, NT, smemB>>>(z0, h, W, bias, out);
}

// round 12
// speedup vs baseline: 1.1721x; 1.1721x over previous
#include <cuda_runtime.h>
#include <math.h>

#define HALF_DT 0.005f
#define BATCH 32
#define DM    2048
#define DV    2047
#define DL    512
#define DPC   16            // output d-rows per CTA
#define HALO  2
#define ROWS  20            // DPC + 2*HALO
#define NT    512
#define GRID  128
#define ZS    516           // z/w row stride (conflict-free LDS.128)
#define EST   33            // epilogue tile stride

// smem: zs [32][516] then ws [20][516]; epilogue tiles alias zs region.
#define WS_OFF   (BATCH * ZS)          // 16512
#define SMEM_FLT (WS_OFF + ROWS * ZS)  // 26832 floats = 107328 B
#define P_OFF    0                     // part [20][132]
#define SV_OFF   2640                  // svt [20][33]
#define HT_OFF   3300                  // ht  [20][33]
#define Y1_OFF   3960                  // y1  [20][33]

extern __shared__ float smem[];

__global__ void __launch_bounds__(NT, 1)
fused_kernel(const float* __restrict__ z0,
             const float* __restrict__ h,
             const float* __restrict__ W,
             const float* __restrict__ bias,
             float* __restrict__ out) {
    const int tid   = threadIdx.x;
    const int lane  = tid & 31;
    const int w     = tid >> 5;          // 0..15
    const int kq    = w >> 2;            // 0..3  (K quarter)
    const int rg    = w & 3;             // 0..3  (row group of 5)
    const int dbase = blockIdx.x * DPC;

    float* zs = smem;
    float* ws = smem + WS_OFF;

    // ---- stage z0 (full, 4096 f4) and W tile (20 rows, 2560 f4), coalesced ----
    for (int i = tid; i < BATCH * (DL / 4); i += NT) {
        int b = i >> 7, k4 = i & 127;
        *((float4*)(zs + b * ZS) + k4) = *((const float4*)(z0 + b * DL) + k4);
    }
    for (int i = tid; i < ROWS * (DL / 4); i += NT) {
        int r = i >> 7, k4 = i & 127;
        int d = min(max(dbase + r - HALO, 0), DM - 2);   // W has DV=2047 rows
        *((float4*)(ws + r * ZS) + k4) = *((const float4*)(W + (size_t)d * DL) + k4);
    }
    __syncthreads();

    // ---- mainloop: warp (kq, rg) -> rows rg*5..rg*5+4, k in [kq*128, kq*128+128) ----
    float a[5][4];
#pragma unroll
    for (int j = 0; j < 5; j++)
#pragma unroll
        for (int c = 0; c < 4; c++) a[j][c] = 0.f;
    {
        const float4* zr = (const float4*)(zs + lane * ZS) + kq * 32;
        const float4* w0 = (const float4*)(ws + (rg * 5    ) * ZS) + kq * 32;
        const float4* w1 = (const float4*)(ws + (rg * 5 + 1) * ZS) + kq * 32;
        const float4* w2 = (const float4*)(ws + (rg * 5 + 2) * ZS) + kq * 32;
        const float4* w3 = (const float4*)(ws + (rg * 5 + 3) * ZS) + kq * 32;
        const float4* w4 = (const float4*)(ws + (rg * 5 + 4) * ZS) + kq * 32;
#pragma unroll 8
        for (int k = 0; k < 32; k++) {
            float4 z = zr[k];
            float4 p;
            p = w0[k]; a[0][0] += z.x*p.x; a[0][1] += z.y*p.y; a[0][2] += z.z*p.z; a[0][3] += z.w*p.w;
            p = w1[k]; a[1][0] += z.x*p.x; a[1][1] += z.y*p.y; a[1][2] += z.z*p.z; a[1][3] += z.w*p.w;
            p = w2[k]; a[2][0] += z.x*p.x; a[2][1] += z.y*p.y; a[2][2] += z.z*p.z; a[2][3] += z.w*p.w;
            p = w3[k]; a[3][0] += z.x*p.x; a[3][1] += z.y*p.y; a[3][2] += z.z*p.z; a[3][3] += z.w*p.w;
            p = w4[k]; a[4][0] += z.x*p.x; a[4][1] += z.y*p.y; a[4][2] += z.z*p.z; a[4][3] += z.w*p.w;
        }
    }
    __syncthreads();                     // zs reads done; alias epilogue tiles onto zs

    // ---- write K-partials: part[r][kq][lane] ----
    float* part = smem + P_OFF;
#pragma unroll
    for (int j = 0; j < 5; j++) {
        float s = (a[j][0] + a[j][1]) + (a[j][2] + a[j][3]);
        part[(rg * 5 + j) * 132 + kq * 33 + lane] = s;
    }
    __syncthreads();

    // ---- reduce K-partials -> sv = HALF_DT*tanh(.+bias), and stage h tile ----
    float* svt = smem + SV_OFF;
    float* ht  = smem + HT_OFF;
    float* y1  = smem + Y1_OFF;
    for (int idx = tid; idx < ROWS * BATCH; idx += NT) {
        int r = idx >> 5, b = idx & 31;
        float s = (part[r * 132 + b] + part[r * 132 + 33 + b])
                + (part[r * 132 + 66 + b] + part[r * 132 + 99 + b]);
        int d  = dbase + r - HALO;
        int dc = min(max(d, 0), DV - 1);
        svt[r * EST + b] = (d >= 0 && d < DV)
            ? HALF_DT * tanhf(s + __ldg(bias + dc)) : 0.f;
    }
    for (int idx = tid; idx < ROWS * BATCH; idx += NT) {
        int b = idx / ROWS, r = idx - b * ROWS;
        int d = min(max(dbase + r - HALO, 0), DM - 1);
        ht[r * EST + b] = h[(size_t)b * DM + d];
    }
    __syncthreads();

    // ---- pass 1: y1 = N h, rows 1..18 ----
    for (int idx = tid; idx < BATCH * (ROWS - 2); idx += NT) {
        int r = (idx >> 5) + 1, b = idx & 31;
        y1[r * EST + b] = svt[r * EST + b] * ht[(r + 1) * EST + b]
                        - svt[(r - 1) * EST + b] * ht[(r - 1) * EST + b];
    }
    __syncthreads();

    // ---- output: x = h + 2*(y1 + y2),  y2 = N y1 computed in registers ----
    {
        int b = tid >> 4, j = tid & 15;
        int r = j + HALO;                    // rows 2..17 -> d = dbase..dbase+15
        float y2 = svt[r * EST + b] * y1[(r + 1) * EST + b]
                 - svt[(r - 1) * EST + b] * y1[(r - 1) * EST + b];
        float x = ht[r * EST + b] + 2.f * (y1[r * EST + b] + y2);
        out[(size_t)b * DM + dbase + j] = x;
    }
}

// ---------------------------------------------------------------------------
extern "C" void kernel_launch(void* const* d_in, const int* in_sizes, int n_in,
                              void* d_out, int out_size) {
    const float* z0   = (const float*)d_in[0];   // (32, 512)
    const float* h    = (const float*)d_in[1];   // (32, 2048)
    const float* W    = (const float*)d_in[2];   // (2047, 512)
    const float* bias = (const float*)d_in[3];   // (2047,)
    float* out = (float*)d_out;                  // (32, 2048)

    const int smemB = SMEM_FLT * (int)sizeof(float);   // 107328 B
    static bool attr_done = false;
    if (!attr_done) {
        cudaFuncSetAttribute(fused_kernel,
                             cudaFuncAttributeMaxDynamicSharedMemorySize, smemB);
        attr_done = true;
    }
    fused_kernel<<<GRID, NT, smemB>>>(z0, h, W, bias, out);
}